// round 5
// baseline (speedup 1.0000x reference)
#include <cuda_runtime.h>
#include <math.h>

#define Nn 1395
#define Ee 44640
#define FC1_BLOCKS 540
#define FC1_ROWS   496   // 540*496 = 267840
#define FC2_BLOCKS 128
#define FC2_ROWS   8     // 128*8 = 1024

// ---------------- scratch (device globals, allocation-free) ----------------
__device__ float g_deg [Nn];
__device__ float g_dinv[Nn];
__device__ __align__(16) float g_h0[Nn * 32];   // gcn1 transformed
__device__ __align__(16) float g_a1[Nn * 32];   // gcn1 aggregate
__device__ __align__(16) float g_h1[Nn * 32];   // gcn1 output
__device__ __align__(16) float g_t2[Nn * 30];   // gcn2 transformed
__device__ __align__(16) float g_a2[Nn * 30];   // gcn2 aggregate
__device__ __align__(16) float g_h2[Nn * 30];   // gcn2 output
__device__ __align__(16) float g_v [Nn * 192];  // flattened QConv output (267840)
__device__ __align__(16) float g_p1[FC1_BLOCKS * 1024];
__device__ __align__(16) float g_v1[1024];
__device__ __align__(16) float g_p2[FC2_BLOCKS * 1024];
__device__ __align__(16) float g_v2[1024];

// ---------------- init: deg=1 (self loop), zero aggregates -----------------
__global__ void k_init() {
    int i = blockIdx.x * blockDim.x + threadIdx.x;
    if (i < Nn)      g_deg[i] = 1.0f;
    if (i < Nn * 32) g_a1[i] = 0.0f;
    if (i < Nn * 30) g_a2[i] = 0.0f;
}

// deg[dst] += 1 over E edges (exact small-int float adds -> deterministic)
__global__ void k_deg(const int* __restrict__ ei) {
    int e = blockIdx.x * blockDim.x + threadIdx.x;
    if (e < Ee) atomicAdd(&g_deg[ei[Ee + e]], 1.0f);
}

__global__ void k_dinv() {
    int i = blockIdx.x * blockDim.x + threadIdx.x;
    if (i < Nn) g_dinv[i] = rsqrtf(g_deg[i]);
}

// ---------------- GCN layer 1: transform (x[:, :3] == 0, so only f=3..5) ---
__global__ void k_t1(const float* __restrict__ x, const float* __restrict__ w1) {
    int i = blockIdx.x * blockDim.x + threadIdx.x;
    if (i >= Nn * 32) return;
    int n = i >> 5, c = i & 31;
    float acc = x[n * 6 + 3] * w1[3 * 32 + c]
              + x[n * 6 + 4] * w1[4 * 32 + c]
              + x[n * 6 + 5] * w1[5 * 32 + c];
    g_h0[i] = acc;
}

// edge-parallel aggregate: warp per edge, lane per channel
__global__ void k_agg1(const int* __restrict__ ei) {
    int i = blockIdx.x * blockDim.x + threadIdx.x;
    if (i >= Ee * 32) return;
    int e = i >> 5, c = i & 31;
    int s = ei[e], d = ei[Ee + e];
    float coef = g_dinv[s] * g_dinv[d];
    atomicAdd(&g_a1[d * 32 + c], coef * g_h0[s * 32 + c]);
}

// self-loop term + bias + LeakyReLU(0.2)
__global__ void k_fin1(const float* __restrict__ b1) {
    int i = blockIdx.x * blockDim.x + threadIdx.x;
    if (i >= Nn * 32) return;
    int n = i >> 5, c = i & 31;
    float di = g_dinv[n];
    float v = g_a1[i] + di * di * g_h0[i] + b1[c];
    g_h1[i] = v > 0.0f ? v : 0.2f * v;
}

// ---------------- GCN layer 2: 32 -> 30 ------------------------------------
__global__ void k_t2(const float* __restrict__ w2) {
    int i = blockIdx.x * blockDim.x + threadIdx.x;
    if (i >= Nn * 30) return;
    int n = i / 30, c = i % 30;
    float acc = 0.0f;
#pragma unroll
    for (int k = 0; k < 32; k++)
        acc += g_h1[n * 32 + k] * __ldg(&w2[k * 30 + c]);
    g_t2[i] = acc;
}

__global__ void k_agg2(const int* __restrict__ ei) {
    int i = blockIdx.x * blockDim.x + threadIdx.x;
    if (i >= Ee * 32) return;
    int e = i >> 5, c = i & 31;
    if (c >= 30) return;
    int s = ei[e], d = ei[Ee + e];
    float coef = g_dinv[s] * g_dinv[d];
    atomicAdd(&g_a2[d * 30 + c], coef * g_t2[s * 30 + c]);
}

__global__ void k_fin2(const float* __restrict__ b2) {
    int i = blockIdx.x * blockDim.x + threadIdx.x;
    if (i >= Nn * 30) return;
    int n = i / 30, c = i % 30;
    float di = g_dinv[n];
    float v = g_a2[i] + di * di * g_t2[i] + b2[c];
    g_h2[i] = v > 0.0f ? v : 0.2f * v;
}

// ---------------- fused QConv chain: 30->192->192->192 ---------------------
// 5 nodes per block (279 * 5 = 1395), thread = output channel (192 threads).
__global__ void k_qfused(const float* __restrict__ qw1, const float* __restrict__ qb1,
                         const float* __restrict__ qw2, const float* __restrict__ qb2,
                         const float* __restrict__ qw3, const float* __restrict__ qb3) {
    __shared__ float s_in[5][30];
    __shared__ float sa[5][192];
    __shared__ float sb[5][192];
    int nb = blockIdx.x * 5;
    int c  = threadIdx.x;

    for (int i = c; i < 5 * 30; i += 192)
        s_in[i / 30][i % 30] = g_h2[nb * 30 + i];
    __syncthreads();

    float acc[5];
#pragma unroll
    for (int g = 0; g < 5; g++) acc[g] = qb1[c];
#pragma unroll
    for (int k = 0; k < 30; k++) {
        float w = __ldg(&qw1[k * 192 + c]);
#pragma unroll
        for (int g = 0; g < 5; g++) acc[g] += s_in[g][k] * w;
    }
#pragma unroll
    for (int g = 0; g < 5; g++) sa[g][c] = acc[g];
    __syncthreads();

#pragma unroll
    for (int g = 0; g < 5; g++) acc[g] = qb2[c];
#pragma unroll 8
    for (int k = 0; k < 192; k++) {
        float w = __ldg(&qw2[k * 192 + c]);
#pragma unroll
        for (int g = 0; g < 5; g++) acc[g] += sa[g][k] * w;
    }
#pragma unroll
    for (int g = 0; g < 5; g++) sb[g][c] = acc[g];
    __syncthreads();

#pragma unroll
    for (int g = 0; g < 5; g++) acc[g] = qb3[c];
#pragma unroll 8
    for (int k = 0; k < 192; k++) {
        float w = __ldg(&qw3[k * 192 + c]);
#pragma unroll
        for (int g = 0; g < 5; g++) acc[g] += sb[g][k] * w;
    }
#pragma unroll
    for (int g = 0; g < 5; g++)
        g_v[(nb + g) * 192 + c] = acc[g];
}

// ---------------- fc1: v[267840] @ fw1[267840,1024] (the HBM monster) ------
// 540 blocks * 496 rows; 256 threads, each thread owns 4 contiguous columns.
__global__ void __launch_bounds__(256) k_fc1_part(const float* __restrict__ fw1) {
    int r0 = blockIdx.x * FC1_ROWS;
    int j4 = threadIdx.x * 4;
    const float4* W = (const float4*)(fw1 + (size_t)r0 * 1024 + j4);
    float4 acc = make_float4(0.f, 0.f, 0.f, 0.f);
#pragma unroll 8
    for (int r = 0; r < FC1_ROWS; r++) {
        float vv = __ldg(&g_v[r0 + r]);
        float4 w = __ldg(W);
        W += 256;  // next row (1024 floats / 4)
        acc.x += vv * w.x; acc.y += vv * w.y;
        acc.z += vv * w.z; acc.w += vv * w.w;
    }
    *(float4*)(g_p1 + blockIdx.x * 1024 + j4) = acc;
}

__global__ void k_fc1_red(const float* __restrict__ fb1) {
    int j = blockIdx.x * blockDim.x + threadIdx.x;  // 0..1023
    float s = 0.0f;
#pragma unroll 4
    for (int b = 0; b < FC1_BLOCKS; b++) s += g_p1[b * 1024 + j];
    g_v1[j] = s + fb1[j];
}

// ---------------- fc2: 1024 -> 1024 ----------------------------------------
__global__ void __launch_bounds__(256) k_fc2_part(const float* __restrict__ fw2) {
    int r0 = blockIdx.x * FC2_ROWS;
    int j4 = threadIdx.x * 4;
    const float4* W = (const float4*)(fw2 + (size_t)r0 * 1024 + j4);
    float4 acc = make_float4(0.f, 0.f, 0.f, 0.f);
#pragma unroll
    for (int r = 0; r < FC2_ROWS; r++) {
        float vv = g_v1[r0 + r];
        float4 w = __ldg(W);
        W += 256;
        acc.x += vv * w.x; acc.y += vv * w.y;
        acc.z += vv * w.z; acc.w += vv * w.w;
    }
    *(float4*)(g_p2 + blockIdx.x * 1024 + j4) = acc;
}

__global__ void k_fc2_red(const float* __restrict__ fb2) {
    int j = blockIdx.x * blockDim.x + threadIdx.x;
    float s = 0.0f;
#pragma unroll 4
    for (int b = 0; b < FC2_BLOCKS; b++) s += g_p2[b * 1024 + j];
    g_v2[j] = s + fb2[j];
}

// ---------------- fc3 (1024->64) + quaternion group-of-4 normalize ---------
__global__ void k_fc3(const float* __restrict__ fw3, const float* __restrict__ fb3,
                      float* __restrict__ out) {
    __shared__ float s[4][64];
    __shared__ float s2[64];
    __shared__ float mag[16];
    int t = threadIdx.x;              // 256 threads
    int j = t & 63, ch = t >> 6;      // 4 row-chunks of 256
    float acc = 0.0f;
    int r0 = ch * 256;
#pragma unroll 8
    for (int r = 0; r < 256; r++)
        acc += g_v2[r0 + r] * __ldg(&fw3[(r0 + r) * 64 + j]);
    s[ch][j] = acc;
    __syncthreads();
    if (t < 64) s2[t] = s[0][t] + s[1][t] + s[2][t] + s[3][t] + fb3[t];
    __syncthreads();
    if (t < 16) {
        float a = s2[4 * t], b = s2[4 * t + 1], c = s2[4 * t + 2], d = s2[4 * t + 3];
        mag[t] = sqrtf(a * a + b * b + c * c + d * d);
    }
    __syncthreads();
    if (t < 64) out[t] = s2[t] / mag[t >> 2];
}

// ---------------- launcher --------------------------------------------------
extern "C" void kernel_launch(void* const* d_in, const int* in_sizes, int n_in,
                              void* d_out, int out_size) {
    const float* x   = (const float*)d_in[0];
    const int*   ei  = (const int*)  d_in[1];
    const float* w1  = (const float*)d_in[2];
    const float* b1  = (const float*)d_in[3];
    const float* w2  = (const float*)d_in[4];
    const float* b2  = (const float*)d_in[5];
    const float* qw1 = (const float*)d_in[6];
    const float* qb1 = (const float*)d_in[7];
    const float* qw2 = (const float*)d_in[8];
    const float* qb2 = (const float*)d_in[9];
    const float* qw3 = (const float*)d_in[10];
    const float* qb3 = (const float*)d_in[11];
    const float* fw1 = (const float*)d_in[12];
    const float* fb1 = (const float*)d_in[13];
    const float* fw2 = (const float*)d_in[14];
    const float* fb2 = (const float*)d_in[15];
    const float* fw3 = (const float*)d_in[16];
    const float* fb3 = (const float*)d_in[17];
    float* out = (float*)d_out;

    const int T = 256;
    int g_n32 = (Nn * 32 + T - 1) / T;      // 175 (== (Ee+T-1)/T, Ee = Nn*32)
    int g_n30 = (Nn * 30 + T - 1) / T;      // 164
    int g_n   = (Nn + T - 1) / T;           // 6
    int g_e32 = (Ee * 32 + T - 1) / T;      // 5580

    k_init <<<g_n32, T>>>();
    k_deg  <<<g_n32, T>>>(ei);
    k_dinv <<<g_n,   T>>>();

    k_t1   <<<g_n32, T>>>(x, w1);
    k_agg1 <<<g_e32, T>>>(ei);
    k_fin1 <<<g_n32, T>>>(b1);

    k_t2   <<<g_n30, T>>>(w2);
    k_agg2 <<<g_e32, T>>>(ei);
    k_fin2 <<<g_n30, T>>>(b2);

    k_qfused <<<279, 192>>>(qw1, qb1, qw2, qb2, qw3, qb3);

    k_fc1_part <<<FC1_BLOCKS, 256>>>(fw1);
    k_fc1_red  <<<4, 256>>>(fb1);
    k_fc2_part <<<FC2_BLOCKS, 256>>>(fw2);
    k_fc2_red  <<<4, 256>>>(fb2);
    k_fc3      <<<1, 256>>>(fw3, fb3, out);
}